// round 3
// baseline (speedup 1.0000x reference)
#include <cuda_runtime.h>
#include <cstdint>

#define G  256
#define NV 512
#define NE 4096
#define FI 64
#define FO 64
#define NC 16
#define KFLAT (NV*FO)      // 32768
#define KC 512
#define KCH (KFLAT/KC)     // 64

// -------- scratch (no allocations allowed; device globals are the sanctioned path) ----
__device__ float g_xw[(size_t)G*NV*FO];        // 33.5 MB
__device__ float g_h [(size_t)G*NV*FO];        // 33.5 MB
__device__ float g_part[(size_t)KCH*G*NC];     // 1 MB, deterministic split-K partials

// =====================================================================================
// K1: xw[g,n,o] = sum_f x[g,n,f] * W[o,f]   — packed f32x2 FMA over the f (K) dimension
// Block: 64 nodes x 64 outs of one graph. 256 threads, thread tile 4 nodes x 4 outs.
// Accumulator pairs hold (even-f, odd-f) partial sums; horizontal add at the end.
// =====================================================================================
__global__ __launch_bounds__(256) void k_xw(const float* __restrict__ x,
                                            const float* __restrict__ W) {
    __shared__ float xs[64*68];   // stride 68: even (=> .64 aligned), <=2-way conflicts
    __shared__ float ws[64*68];
    const int g  = blockIdx.y;
    const int n0 = blockIdx.x * 64;
    const int tid = threadIdx.x;

    const float* xg = x + ((size_t)g*NV + n0) * FI;
    for (int i = tid; i < 64*64; i += 256) {
        int n = i >> 6, f = i & 63;
        xs[n*68 + f] = xg[i];
    }
    for (int i = tid; i < 64*64; i += 256) {
        int o = i >> 6, f = i & 63;
        ws[o*68 + f] = W[i];
    }
    __syncthreads();

    const int tx = tid & 15, ty = tid >> 4;
    const int nb = ty * 4, ob = tx * 4;

    unsigned long long acc[4][4];
#pragma unroll
    for (int i = 0; i < 4; i++)
#pragma unroll
        for (int j = 0; j < 4; j++) acc[i][j] = 0ull;

#pragma unroll 4
    for (int f = 0; f < 64; f += 2) {
        unsigned long long a[4], b[4];
#pragma unroll
        for (int i = 0; i < 4; i++)
            a[i] = *(const unsigned long long*)&xs[(nb+i)*68 + f];
#pragma unroll
        for (int j = 0; j < 4; j++)
            b[j] = *(const unsigned long long*)&ws[(ob+j)*68 + f];
#pragma unroll
        for (int i = 0; i < 4; i++)
#pragma unroll
            for (int j = 0; j < 4; j++)
                asm("fma.rn.f32x2 %0, %1, %2, %0;"
                    : "+l"(acc[i][j]) : "l"(a[i]), "l"(b[j]));
    }

    float* outp = g_xw + ((size_t)g*NV + n0) * FO;
#pragma unroll
    for (int i = 0; i < 4; i++) {
        float v[4];
#pragma unroll
        for (int j = 0; j < 4; j++) {
            unsigned lo = (unsigned)(acc[i][j] & 0xffffffffull);
            unsigned hi = (unsigned)(acc[i][j] >> 32);
            v[j] = __uint_as_float(lo) + __uint_as_float(hi);
        }
        *(float4*)&outp[(nb+i)*FO + ob] = make_float4(v[0], v[1], v[2], v[3]);
    }
}

// =====================================================================================
// K2: one CTA per graph (512 threads). deg/rsqrt -> CSR counting sort -> stage xw in
// smem -> warp-per-node gather aggregation (+self-loop, +bias, ReLU) -> g_h.
// Dyn smem: xs 128K | dinv 2K | rowptr 2052 | offs 2K | csr 16K | wtmp 64  ~= 150 KB
// =====================================================================================
#define K2_SMEM (NV*FO*4 + NV*4 + (NV+1)*4 + NV*4 + NE*4 + 16*4)

__global__ __launch_bounds__(512) void k_graph(const int* __restrict__ eidx,
                                               const float* __restrict__ cbias) {
    extern __shared__ char smraw[];
    float* xs     = (float*)smraw;            // NV*FO
    float* dinv   = xs + NV*FO;               // NV
    int*   rowptr = (int*)(dinv + NV);        // NV+1
    int*   offs   = rowptr + NV + 1;          // NV
    int*   csr    = offs + NV;                // NE
    int*   wtmp   = csr + NE;                 // 16

    const int g   = blockIdx.x;
    const int tid = threadIdx.x;
    const int lane = tid & 31, wrp = tid >> 5;
    const int* src = eidx + (size_t)g*2*NE;
    const int* tgt = src + NE;

    // in-degree histogram (offs doubles as the counter array)
    offs[tid] = 0;
    __syncthreads();
    for (int e = tid; e < NE; e += 512) atomicAdd(&offs[tgt[e]], 1);
    __syncthreads();

    const int cnt = offs[tid];
    dinv[tid] = rsqrtf((float)(cnt + 1));     // +1 self-loop; deg always > 0

    // block-wide exclusive scan of cnt (16 warps of 32)
    int v = cnt;
#pragma unroll
    for (int d = 1; d < 32; d <<= 1) {
        int t = __shfl_up_sync(0xffffffffu, v, d);
        if (lane >= d) v += t;
    }
    if (lane == 31) wtmp[wrp] = v;
    __syncthreads();
    if (wrp == 0) {
        int wv = (lane < 16) ? wtmp[lane] : 0;
#pragma unroll
        for (int d = 1; d < 16; d <<= 1) {
            int t = __shfl_up_sync(0xffffffffu, wv, d);
            if (lane >= d) wv += t;
        }
        if (lane < 16) wtmp[lane] = wv;       // inclusive per-warp sums
    }
    __syncthreads();
    const int base = (wrp > 0) ? wtmp[wrp-1] : 0;
    const int excl = base + (v - cnt);
    rowptr[tid] = excl;
    offs[tid]   = excl;
    if (tid == 0) rowptr[NV] = NE;
    __syncthreads();

    // place edges sorted by target
    for (int e = tid; e < NE; e += 512) {
        int c = tgt[e];
        int p = atomicAdd(&offs[c], 1);
        csr[p] = src[e];
    }

    // stage this graph's xw into smem (vectorized)
    const float4* xw4 = (const float4*)(g_xw + (size_t)g*NV*FO);
    float4* xs4 = (float4*)xs;
    for (int i = tid; i < NV*FO/4; i += 512) xs4[i] = xw4[i];
    __syncthreads();

    // warp-per-node gather; lane owns 2 consecutive features
    const float b0 = cbias[2*lane];
    const float b1 = cbias[2*lane + 1];
    for (int n = wrp*32; n < wrp*32 + 32; n++) {
        const float d = dinv[n];
        float2 xv = *(const float2*)&xs[n*FO + 2*lane];
        float a0 = xv.x * (d*d);
        float a1 = xv.y * (d*d);
        const int beg = rowptr[n], end = rowptr[n+1];
        for (int j = beg; j < end; j++) {
            const int s = csr[j];
            const float nrm = dinv[s] * d;
            float2 m = *(const float2*)&xs[s*FO + 2*lane];
            a0 = fmaf(m.x, nrm, a0);
            a1 = fmaf(m.y, nrm, a1);
        }
        float2 o;
        o.x = fmaxf(a0 + b0, 0.f);
        o.y = fmaxf(a1 + b1, 0.f);
        *(float2*)&g_h[((size_t)g*NV + n)*FO + 2*lane] = o;
    }
}

// =====================================================================================
// K3: split-K logits GEMM. Block = 32 graphs x 16 classes x K-chunk 512.
// Weight chunk transposed in smem (stride 17 -> conflict-free); h reads are
// warp-broadcast LDG. Deterministic per-chunk partials (no float atomics).
// =====================================================================================
__global__ __launch_bounds__(256) void k_lin(const float* __restrict__ lw) {
    __shared__ float ws[KC*17];
    const int bx = blockIdx.x;     // 8 graph tiles of 32
    const int by = blockIdx.y;     // KCH k-chunks
    const int tid = threadIdx.x;
    const int k0 = by * KC;

    for (int i = tid; i < NC*KC; i += 256) {
        int c  = i >> 9;           // / KC
        int kk = i & (KC-1);
        ws[kk*17 + c] = lw[(size_t)c*KFLAT + k0 + kk];
    }
    __syncthreads();

    const int c  = tid & 15;
    const int gp = tid >> 4;
    const int g0 = bx*32 + gp*2;
    const float* h0 = g_h + (size_t)g0*KFLAT + k0;
    const float* h1 = h0 + KFLAT;

    float a0 = 0.f, a1 = 0.f;
#pragma unroll 8
    for (int k = 0; k < KC; k++) {
        float w = ws[k*17 + c];
        a0 = fmaf(h0[k], w, a0);
        a1 = fmaf(h1[k], w, a1);
    }
    g_part[((size_t)by*G + g0    )*NC + c] = a0;
    g_part[((size_t)by*G + g0 + 1)*NC + c] = a1;
}

// =====================================================================================
// K4: deterministic partial reduction + bias + log_softmax (16-lane shfl reductions)
// =====================================================================================
__global__ __launch_bounds__(256) void k_sm(const float* __restrict__ lbias,
                                            float* __restrict__ out) {
    const int tid = threadIdx.x;
    const int c  = tid & 15;
    const int gl = tid >> 4;
    const int g  = blockIdx.x*16 + gl;

    float v = lbias[c];
    for (int p = 0; p < KCH; p++)
        v += g_part[((size_t)p*G + g)*NC + c];

    float m = v;
#pragma unroll
    for (int d = 8; d >= 1; d >>= 1)
        m = fmaxf(m, __shfl_xor_sync(0xffffffffu, m, d));
    float s = expf(v - m);
#pragma unroll
    for (int d = 8; d >= 1; d >>= 1)
        s += __shfl_xor_sync(0xffffffffu, s, d);

    out[(size_t)g*NC + c] = (v - m) - logf(s);
}

// =====================================================================================
extern "C" void kernel_launch(void* const* d_in, const int* in_sizes, int n_in,
                              void* d_out, int out_size) {
    const float* x  = (const float*)d_in[0];   // [G,NV,FI]
    const int*   ei = (const int*)  d_in[1];   // [G,2,NE]
    const float* cw = (const float*)d_in[2];   // [FO,FI]
    const float* cb = (const float*)d_in[3];   // [FO]
    const float* lw = (const float*)d_in[4];   // [NC, KFLAT]
    const float* lb = (const float*)d_in[5];   // [NC]
    float* out = (float*)d_out;                // [G,NC]

    (void)in_sizes; (void)n_in; (void)out_size;

    cudaFuncSetAttribute(k_graph, cudaFuncAttributeMaxDynamicSharedMemorySize, K2_SMEM);

    k_xw  <<<dim3(NV/64, G), 256>>>(x, cw);
    k_graph<<<G, 512, K2_SMEM>>>(ei, cb);
    k_lin <<<dim3(G/32, KCH), 256>>>(lw);
    k_sm  <<<G/16, 256>>>(lb, out);
}

// round 5
// speedup vs baseline: 1.3370x; 1.3370x over previous
#include <cuda_runtime.h>
#include <cstdint>

#define G  256
#define NV 512
#define NE 4096
#define FI 64
#define FO 64
#define NC 16
#define KFLAT (NV*FO)      // 32768

// -------- scratch (device globals: the sanctioned no-alloc path) --------------------
__device__ float g_xw[(size_t)G*NV*FO];          // 33.5 MB
__device__ float g_h [(size_t)G*NV*FO];          // 33.5 MB
__device__ float g_part[(size_t)G*512*NC];       // 8 MB: [g][kseg 0..511][c]

#define FMA2(acc, a, b) asm("fma.rn.f32x2 %0, %1, %2, %0;" : "+l"(acc) : "l"(a), "l"(b))

// =====================================================================================
// K1: xw[g,n,o] = sum_f x[g,n,f] * W[o,f]
// CTA tile 128n x 64o, 256 threads, thread tile 8n x 4o, packed f32x2 over f.
// W smem is XOR-swizzled: ws[o*64 + (f ^ 2*((o>>2)&15))] -> lane tx reading row
// o=4tx+j hits bank (f ^ 2tx): all 32 banks exactly once per LDS.64 -> conflict-free.
// a-operand (xs) is 2-address broadcast per warp -> banks irrelevant.
// =====================================================================================
__global__ __launch_bounds__(256) void k_xw(const float* __restrict__ x,
                                            const float* __restrict__ W) {
    __shared__ float xs[128*64];   // 32 KB
    __shared__ float ws[64*64];    // 16 KB (swizzled)
    const int g  = blockIdx.y;
    const int n0 = blockIdx.x * 128;
    const int tid = threadIdx.x;

    // stage x tile (coalesced float4, conflict-free stores)
    const float4* xg4 = (const float4*)(x + ((size_t)g*NV + n0) * FI);
    float4* xs4 = (float4*)xs;
    for (int i = tid; i < 128*64/4; i += 256) xs4[i] = xg4[i];

    // stage W with pair-granular XOR swizzle
    for (int i = tid; i < 64*64/2; i += 256) {
        int o  = i >> 5;
        int fp = (i & 31) * 2;
        int fs = fp ^ (2*((o >> 2) & 15));
        *(unsigned long long*)&ws[o*64 + fs] =
            *(const unsigned long long*)&W[o*64 + fp];
    }
    __syncthreads();

    const int tx = tid & 15, ny = tid >> 4;
    const int nb = ny * 8, ob = tx * 4, sw = 2 * tx;

    unsigned long long acc[8][4];
#pragma unroll
    for (int i = 0; i < 8; i++)
#pragma unroll
        for (int j = 0; j < 4; j++) acc[i][j] = 0ull;

#pragma unroll
    for (int f = 0; f < 64; f += 4) {
        unsigned long long b0[4], b1[4];
#pragma unroll
        for (int j = 0; j < 4; j++) {
            b0[j] = *(const unsigned long long*)&ws[(ob+j)*64 + ( f      ^ sw)];
            b1[j] = *(const unsigned long long*)&ws[(ob+j)*64 + ((f + 2) ^ sw)];
        }
#pragma unroll
        for (int i = 0; i < 8; i++) {
            ulonglong2 a2 = *(const ulonglong2*)&xs[(nb+i)*64 + f];
#pragma unroll
            for (int j = 0; j < 4; j++) {
                FMA2(acc[i][j], a2.x, b0[j]);
                FMA2(acc[i][j], a2.y, b1[j]);
            }
        }
    }

    float* outp = g_xw + ((size_t)g*NV + n0) * FO;
#pragma unroll
    for (int i = 0; i < 8; i++) {
        float v[4];
#pragma unroll
        for (int j = 0; j < 4; j++) {
            unsigned lo = (unsigned)(acc[i][j] & 0xffffffffull);
            unsigned hi = (unsigned)(acc[i][j] >> 32);
            v[j] = __uint_as_float(lo) + __uint_as_float(hi);
        }
        *(float4*)&outp[(nb+i)*FO + ob] = make_float4(v[0], v[1], v[2], v[3]);
    }
}

// =====================================================================================
// K2: one CTA per graph (512 threads). deg/rsqrt -> CSR counting sort -> stage xw in
// smem -> warp-per-node gather (+self-loop, +bias, ReLU) -> g_h.   ~150 KB dyn smem.
// =====================================================================================
#define K2_SMEM (NV*FO*4 + NV*4 + (NV+1)*4 + NV*4 + NE*4 + 16*4)

__global__ __launch_bounds__(512) void k_graph(const int* __restrict__ eidx,
                                               const float* __restrict__ cbias) {
    extern __shared__ char smraw[];
    float* xs     = (float*)smraw;            // NV*FO
    float* dinv   = xs + NV*FO;               // NV
    int*   rowptr = (int*)(dinv + NV);        // NV+1
    int*   offs   = rowptr + NV + 1;          // NV
    int*   csr    = offs + NV;                // NE
    int*   wtmp   = csr + NE;                 // 16

    const int g   = blockIdx.x;
    const int tid = threadIdx.x;
    const int lane = tid & 31, wrp = tid >> 5;
    const int* src = eidx + (size_t)g*2*NE;
    const int* tgt = src + NE;

    offs[tid] = 0;
    __syncthreads();
    for (int e = tid; e < NE; e += 512) atomicAdd(&offs[tgt[e]], 1);
    __syncthreads();

    const int cnt = offs[tid];
    dinv[tid] = rsqrtf((float)(cnt + 1));

    int v = cnt;
#pragma unroll
    for (int d = 1; d < 32; d <<= 1) {
        int t = __shfl_up_sync(0xffffffffu, v, d);
        if (lane >= d) v += t;
    }
    if (lane == 31) wtmp[wrp] = v;
    __syncthreads();
    if (wrp == 0) {
        int wv = (lane < 16) ? wtmp[lane] : 0;
#pragma unroll
        for (int d = 1; d < 16; d <<= 1) {
            int t = __shfl_up_sync(0xffffffffu, wv, d);
            if (lane >= d) wv += t;
        }
        if (lane < 16) wtmp[lane] = wv;
    }
    __syncthreads();
    const int base = (wrp > 0) ? wtmp[wrp-1] : 0;
    const int excl = base + (v - cnt);
    rowptr[tid] = excl;
    offs[tid]   = excl;
    if (tid == 0) rowptr[NV] = NE;
    __syncthreads();

    for (int e = tid; e < NE; e += 512) {
        int c = tgt[e];
        int p = atomicAdd(&offs[c], 1);
        csr[p] = src[e];
    }

    const float4* xw4 = (const float4*)(g_xw + (size_t)g*NV*FO);
    float4* xs4 = (float4*)xs;
    for (int i = tid; i < NV*FO/4; i += 512) xs4[i] = xw4[i];
    __syncthreads();

    const float b0 = cbias[2*lane];
    const float b1 = cbias[2*lane + 1];
    for (int n = wrp*32; n < wrp*32 + 32; n++) {
        const float d = dinv[n];
        float2 xv = *(const float2*)&xs[n*FO + 2*lane];
        float a0 = xv.x * (d*d);
        float a1 = xv.y * (d*d);
        const int beg = rowptr[n], end = rowptr[n+1];
        for (int j = beg; j < end; j++) {
            const int s = csr[j];
            const float nrm = dinv[s] * d;
            float2 m = *(const float2*)&xs[s*FO + 2*lane];
            a0 = fmaf(m.x, nrm, a0);
            a1 = fmaf(m.y, nrm, a1);
        }
        float2 o;
        o.x = fmaxf(a0 + b0, 0.f);
        o.y = fmaxf(a1 + b1, 0.f);
        *(float2*)&g_h[((size_t)g*NV + n)*FO + 2*lane] = o;
    }
}

// =====================================================================================
// K3: logits split-K, weight-stationary. grid(2 graph-halves, 64 k-chunks), 256 thr.
// warp w owns k-segment by*512 + w*64; lane = (c = lane&15, kh = lane>>4);
// thread holds w[c][32 k] packed f32x2 in regs, loops 128 graphs.
// Deterministic per-warp partials -> g_part[g][seg][c].
// =====================================================================================
__global__ __launch_bounds__(256) void k_lin(const float* __restrict__ lw) {
    const int bx = blockIdx.x;           // graph half
    const int by = blockIdx.y;           // k-chunk of 512
    const int tid = threadIdx.x;
    const int lane = tid & 31, wrp = tid >> 5;
    const int c  = lane & 15;
    const int kh = lane >> 4;
    const int kbase = by*512 + wrp*64 + kh*32;
    const int seg = by*8 + wrp;

    unsigned long long wreg[16];
    const float* wp = lw + (size_t)c*KFLAT + kbase;
#pragma unroll
    for (int p = 0; p < 16; p++)
        wreg[p] = *(const unsigned long long*)&wp[2*p];

    for (int gi = 0; gi < 128; gi++) {
        const int g = bx*128 + gi;
        const float* hp = g_h + (size_t)g*KFLAT + kbase;
        unsigned long long acc = 0ull;
#pragma unroll
        for (int p = 0; p < 8; p++) {
            ulonglong2 hv = *(const ulonglong2*)&hp[4*p];
            FMA2(acc, hv.x, wreg[2*p]);
            FMA2(acc, hv.y, wreg[2*p+1]);
        }
        float s = __uint_as_float((unsigned)(acc & 0xffffffffull))
                + __uint_as_float((unsigned)(acc >> 32));
        s += __shfl_xor_sync(0xffffffffu, s, 16);
        if (kh == 0)
            g_part[((size_t)g*512 + seg)*NC + c] = s;
    }
}

// =====================================================================================
// K4: one block per graph. Sum 512 segments (contiguous 32 KB slab), + bias,
// log_softmax via 16-lane shfl.
// =====================================================================================
__global__ __launch_bounds__(256) void k_sm(const float* __restrict__ lbias,
                                            float* __restrict__ out) {
    __shared__ float red[16][16];
    const int g = blockIdx.x;
    const int t = threadIdx.x;
    const int c = t & 15, sgrp = t >> 4;

    const float* pp = g_part + (size_t)g*512*NC;
    float v = 0.f;
#pragma unroll 8
    for (int s = 0; s < 32; s++)
        v += pp[(sgrp*32 + s)*NC + c];
    red[sgrp][c] = v;
    __syncthreads();

    if (t < 16) {
        float tot = lbias[t];
#pragma unroll
        for (int s = 0; s < 16; s++) tot += red[s][t];

        float m = tot;
#pragma unroll
        for (int d = 8; d >= 1; d >>= 1)
            m = fmaxf(m, __shfl_xor_sync(0x0000ffffu, m, d));
        float e = expf(tot - m);
#pragma unroll
        for (int d = 8; d >= 1; d >>= 1)
            e += __shfl_xor_sync(0x0000ffffu, e, d);

        out[(size_t)g*NC + t] = (tot - m) - logf(e);
    }
}

// =====================================================================================
extern "C" void kernel_launch(void* const* d_in, const int* in_sizes, int n_in,
                              void* d_out, int out_size) {
    const float* x  = (const float*)d_in[0];   // [G,NV,FI]
    const int*   ei = (const int*)  d_in[1];   // [G,2,NE]
    const float* cw = (const float*)d_in[2];   // [FO,FI]
    const float* cb = (const float*)d_in[3];   // [FO]
    const float* lw = (const float*)d_in[4];   // [NC,KFLAT]
    const float* lb = (const float*)d_in[5];   // [NC]
    float* out = (float*)d_out;                // [G,NC]

    (void)in_sizes; (void)n_in; (void)out_size;

    cudaFuncSetAttribute(k_graph, cudaFuncAttributeMaxDynamicSharedMemorySize, K2_SMEM);

    k_xw   <<<dim3(NV/128, G), 256>>>(x, cw);
    k_graph<<<G, 512, K2_SMEM>>>(ei, cb);
    k_lin  <<<dim3(2, 64), 256>>>(lw);
    k_sm   <<<G, 256>>>(lb, out);
}

// round 6
// speedup vs baseline: 1.7369x; 1.2992x over previous
#include <cuda_runtime.h>
#include <cstdint>

#define G  256
#define NV 512
#define NE 4096
#define FI 64
#define FO 64
#define NC 16
#define KFLAT (NV*FO)      // 32768

// -------- scratch (device globals: the sanctioned no-alloc path) --------------------
__device__ float g_h [(size_t)G*NV*FO];          // 33.5 MB
__device__ float g_part[(size_t)G*512*NC];       // 8 MB: [g][kseg][c]

#define FMA2(acc, a, b) asm("fma.rn.f32x2 %0, %1, %2, %0;" : "+l"(acc) : "l"(a), "l"(b))

// ---- fused-kernel shared memory layout (byte offsets) ------------------------------
#define SM_XW    0                         // float[NV*FO]    131072 B  (xw result)
#define SM_XSTG  (SM_XW   + NV*FO*4)       // float[128*FI]    32768 B  (x staging)
#define SM_W     (SM_XSTG + 128*FI*4)      // float[FO*FI]     16384 B  (swizzled W)
#define SM_DINV  (SM_W    + FO*FI*4)       // float[NV]
#define SM_ROWP  (SM_DINV + NV*4)          // int[NV+1]
#define SM_OFFS  (SM_ROWP + (NV+1)*4)      // int[NV]
#define SM_CSR   (SM_OFFS + NV*4)          // int[NE]
#define SM_NRM   (SM_CSR  + NE*4)          // float[NE]
#define SM_WTMP  (SM_NRM  + NE*4)          // int[16]
#define SMEM_TOT (SM_WTMP + 64)            // 219204 B total

// =====================================================================================
// Fused: per-graph  xw = x@W^T  (in smem)  ->  GCN aggregate (+bias, ReLU)  -> g_h
// One CTA (512 thr) per graph. GEMM: 4 phases of 128 nodes, thread tile 4n x 4o,
// packed f32x2 over f, XOR-swizzled W smem (conflict-free spread-b reads).
// Aggregation: counting-sort CSR with precomputed edge norms; warp-per-node gather
// unrolled x4 for MLP.
// =====================================================================================
__global__ __launch_bounds__(512) void k_fused(const float* __restrict__ x,
                                               const float* __restrict__ W,
                                               const int* __restrict__ eidx,
                                               const float* __restrict__ cbias) {
    extern __shared__ char sm[];
    float* xw_s  = (float*)(sm + SM_XW);
    float* xstg  = (float*)(sm + SM_XSTG);
    float* w_s   = (float*)(sm + SM_W);
    float* dinv  = (float*)(sm + SM_DINV);
    int*   rowptr= (int*)  (sm + SM_ROWP);
    int*   offs  = (int*)  (sm + SM_OFFS);
    int*   csr   = (int*)  (sm + SM_CSR);
    float* nrmv  = (float*)(sm + SM_NRM);
    int*   wtmp  = (int*)  (sm + SM_WTMP);

    const int g   = blockIdx.x;
    const int tid = threadIdx.x;
    const int lane = tid & 31, wrp = tid >> 5;
    const int* srce = eidx + (size_t)g*2*NE;
    const int* tgte = srce + NE;

    // ---- in-degree histogram ----
    offs[tid] = 0;
    __syncthreads();
    for (int e = tid; e < NE; e += 512) atomicAdd(&offs[tgte[e]], 1);
    __syncthreads();

    const int cnt = offs[tid];
    dinv[tid] = rsqrtf((float)(cnt + 1));      // +1 self-loop

    // ---- block exclusive scan (16 warps) ----
    int v = cnt;
#pragma unroll
    for (int d = 1; d < 32; d <<= 1) {
        int t = __shfl_up_sync(0xffffffffu, v, d);
        if (lane >= d) v += t;
    }
    if (lane == 31) wtmp[wrp] = v;
    __syncthreads();
    if (wrp == 0) {
        int wv = (lane < 16) ? wtmp[lane] : 0;
#pragma unroll
        for (int d = 1; d < 16; d <<= 1) {
            int t = __shfl_up_sync(0xffffffffu, wv, d);
            if (lane >= d) wv += t;
        }
        if (lane < 16) wtmp[lane] = wv;
    }
    __syncthreads();
    const int base = (wrp > 0) ? wtmp[wrp-1] : 0;
    const int excl = base + (v - cnt);
    rowptr[tid] = excl;
    offs[tid]   = excl;
    if (tid == 0) rowptr[NV] = NE;
    __syncthreads();

    // ---- scatter edges sorted by target; precompute edge norms ----
    for (int e = tid; e < NE; e += 512) {
        int s = srce[e], c = tgte[e];
        int p = atomicAdd(&offs[c], 1);
        csr[p]  = s;
        nrmv[p] = dinv[s] * dinv[c];
    }

    // ---- load W with pair-granular XOR swizzle (no sync needed yet) ----
    for (int i = tid; i < FO*FI/2; i += 512) {
        int o  = i >> 5;
        int fp = (i & 31) * 2;
        int fs = fp ^ (2*((o >> 2) & 15));
        *(unsigned long long*)&w_s[o*64 + fs] =
            *(const unsigned long long*)&W[o*64 + fp];
    }

    // ---- GEMM: 4 phases of 128 nodes into xw_s ----
    const int tx = tid & 15, ny = tid >> 4;    // tx: o-group, ny: n-group (0..31)
    const int nb = ny * 4, ob = tx * 4, sw = 2 * tx;

#pragma unroll 1
    for (int p = 0; p < 4; p++) {
        __syncthreads();                        // xstg reuse (covers w_s/scatter 1st time)
        const float4* xg4 = (const float4*)(x + ((size_t)g*NV + p*128) * FI);
        float4* xs4 = (float4*)xstg;
        for (int i = tid; i < 128*FI/4; i += 512) xs4[i] = xg4[i];
        __syncthreads();

        unsigned long long acc[4][4];
#pragma unroll
        for (int i = 0; i < 4; i++)
#pragma unroll
            for (int j = 0; j < 4; j++) acc[i][j] = 0ull;

#pragma unroll
        for (int f = 0; f < 64; f += 4) {
            unsigned long long b0[4], b1[4];
#pragma unroll
            for (int j = 0; j < 4; j++) {
                b0[j] = *(const unsigned long long*)&w_s[(ob+j)*64 + ( f      ^ sw)];
                b1[j] = *(const unsigned long long*)&w_s[(ob+j)*64 + ((f + 2) ^ sw)];
            }
#pragma unroll
            for (int i = 0; i < 4; i++) {
                ulonglong2 a2 = *(const ulonglong2*)&xstg[(nb+i)*64 + f];
#pragma unroll
                for (int j = 0; j < 4; j++) {
                    FMA2(acc[i][j], a2.x, b0[j]);
                    FMA2(acc[i][j], a2.y, b1[j]);
                }
            }
        }
#pragma unroll
        for (int i = 0; i < 4; i++) {
            float vv[4];
#pragma unroll
            for (int j = 0; j < 4; j++) {
                unsigned lo = (unsigned)(acc[i][j] & 0xffffffffull);
                unsigned hi = (unsigned)(acc[i][j] >> 32);
                vv[j] = __uint_as_float(lo) + __uint_as_float(hi);
            }
            *(float4*)&xw_s[(p*128 + nb + i)*64 + ob] = make_float4(vv[0], vv[1], vv[2], vv[3]);
        }
    }
    __syncthreads();                            // xw_s + csr/nrmv all visible

    // ---- gather aggregation: warp per node, lane owns 2 features, unroll x4 ----
    const float bias0 = cbias[2*lane];
    const float bias1 = cbias[2*lane + 1];
    for (int n = wrp*32; n < wrp*32 + 32; n++) {
        const float d = dinv[n];
        float2 xv = *(const float2*)&xw_s[n*FO + 2*lane];
        float a0 = xv.x * (d*d);
        float a1 = xv.y * (d*d);
        int j = rowptr[n];
        const int end = rowptr[n+1];
        for (; j + 4 <= end; j += 4) {
            int s0 = csr[j],   s1 = csr[j+1], s2 = csr[j+2], s3 = csr[j+3];
            float w0 = nrmv[j],   w1 = nrmv[j+1], w2 = nrmv[j+2], w3 = nrmv[j+3];
            float2 m0 = *(const float2*)&xw_s[s0*FO + 2*lane];
            float2 m1 = *(const float2*)&xw_s[s1*FO + 2*lane];
            float2 m2 = *(const float2*)&xw_s[s2*FO + 2*lane];
            float2 m3 = *(const float2*)&xw_s[s3*FO + 2*lane];
            a0 = fmaf(m0.x, w0, a0);  a1 = fmaf(m0.y, w0, a1);
            a0 = fmaf(m1.x, w1, a0);  a1 = fmaf(m1.y, w1, a1);
            a0 = fmaf(m2.x, w2, a0);  a1 = fmaf(m2.y, w2, a1);
            a0 = fmaf(m3.x, w3, a0);  a1 = fmaf(m3.y, w3, a1);
        }
        for (; j < end; j++) {
            int s = csr[j];
            float w = nrmv[j];
            float2 m = *(const float2*)&xw_s[s*FO + 2*lane];
            a0 = fmaf(m.x, w, a0);
            a1 = fmaf(m.y, w, a1);
        }
        float2 o;
        o.x = fmaxf(a0 + bias0, 0.f);
        o.y = fmaxf(a1 + bias1, 0.f);
        *(float2*)&g_h[((size_t)g*NV + n)*FO + 2*lane] = o;
    }
}

// =====================================================================================
// K3: logits split-K, weight-stationary. grid(8 graph-tiles, 64 k-chunks), 256 thr.
// warp w owns k-segment by*512 + w*64; lane = (c = lane&15, kh = lane>>4); thread
// holds w[c][32 k] packed f32x2 in regs, loops 32 graphs. Deterministic partials.
// =====================================================================================
__global__ __launch_bounds__(256) void k_lin(const float* __restrict__ lw) {
    const int bx = blockIdx.x;           // 8 graph tiles of 32
    const int by = blockIdx.y;           // k-chunk of 512
    const int tid = threadIdx.x;
    const int lane = tid & 31, wrp = tid >> 5;
    const int c  = lane & 15;
    const int kh = lane >> 4;
    const int kbase = by*512 + wrp*64 + kh*32;
    const int seg = by*8 + wrp;

    unsigned long long wreg[16];
    const float* wp = lw + (size_t)c*KFLAT + kbase;
#pragma unroll
    for (int p = 0; p < 16; p++)
        wreg[p] = *(const unsigned long long*)&wp[2*p];

    for (int gi = 0; gi < 32; gi++) {
        const int g = bx*32 + gi;
        const float* hp = g_h + (size_t)g*KFLAT + kbase;
        unsigned long long acc = 0ull;
#pragma unroll
        for (int p = 0; p < 8; p++) {
            ulonglong2 hv = *(const ulonglong2*)&hp[4*p];
            FMA2(acc, hv.x, wreg[2*p]);
            FMA2(acc, hv.y, wreg[2*p+1]);
        }
        float s = __uint_as_float((unsigned)(acc & 0xffffffffull))
                + __uint_as_float((unsigned)(acc >> 32));
        s += __shfl_xor_sync(0xffffffffu, s, 16);
        if (kh == 0)
            g_part[((size_t)g*512 + seg)*NC + c] = s;
    }
}

// =====================================================================================
// K4: one block per graph. float4 partial sums (8 LDG.128/thread), smem tree,
// + bias, log_softmax via 16-lane shfl.
// =====================================================================================
__global__ __launch_bounds__(256) void k_sm(const float* __restrict__ lbias,
                                            float* __restrict__ out) {
    __shared__ float red[64][16];
    const int g = blockIdx.x;
    const int t = threadIdx.x;
    const int quad = t & 3, sg = t >> 2;        // sg: 0..63, each owns 8 segs

    const float4* pp4 = (const float4*)(g_part + (size_t)g*512*NC);
    float4 acc = make_float4(0.f, 0.f, 0.f, 0.f);
#pragma unroll
    for (int s8 = 0; s8 < 8; s8++) {
        float4 v = pp4[(sg*8 + s8)*4 + quad];
        acc.x += v.x; acc.y += v.y; acc.z += v.z; acc.w += v.w;
    }
    *(float4*)&red[sg][quad*4] = acc;
    __syncthreads();

    if (t < 16) {
        float tot = lbias[t];
#pragma unroll 8
        for (int s = 0; s < 64; s++) tot += red[s][t];

        float m = tot;
#pragma unroll
        for (int d = 8; d >= 1; d >>= 1)
            m = fmaxf(m, __shfl_xor_sync(0x0000ffffu, m, d));
        float e = expf(tot - m);
#pragma unroll
        for (int d = 8; d >= 1; d >>= 1)
            e += __shfl_xor_sync(0x0000ffffu, e, d);

        out[(size_t)g*NC + t] = (tot - m) - logf(e);
    }
}

// =====================================================================================
extern "C" void kernel_launch(void* const* d_in, const int* in_sizes, int n_in,
                              void* d_out, int out_size) {
    const float* x  = (const float*)d_in[0];   // [G,NV,FI]
    const int*   ei = (const int*)  d_in[1];   // [G,2,NE]
    const float* cw = (const float*)d_in[2];   // [FO,FI]
    const float* cb = (const float*)d_in[3];   // [FO]
    const float* lw = (const float*)d_in[4];   // [NC,KFLAT]
    const float* lb = (const float*)d_in[5];   // [NC]
    float* out = (float*)d_out;                // [G,NC]

    (void)in_sizes; (void)n_in; (void)out_size;

    cudaFuncSetAttribute(k_fused, cudaFuncAttributeMaxDynamicSharedMemorySize, SMEM_TOT);

    k_fused<<<G, 512, SMEM_TOT>>>(x, cw, ei, cb);
    k_lin  <<<dim3(8, 64), 256>>>(lw);
    k_sm   <<<G, 256>>>(lb, out);
}

// round 8
// speedup vs baseline: 2.0583x; 1.1850x over previous
#include <cuda_runtime.h>
#include <cstdint>

#define G  256
#define NV 512
#define NE 4096
#define FI 64
#define FO 64
#define NC 16
#define KFLAT (NV*FO)      // 32768

// -------- scratch (device globals: the sanctioned no-alloc path) --------------------
__device__ float g_h [(size_t)G*NV*FO];          // 33.5 MB
__device__ float g_part[(size_t)G*512*NC];       // 8 MB: [g][kseg][c]

#define FMA2(acc, a, b) asm("fma.rn.f32x2 %0, %1, %2, %0;" : "+l"(acc) : "l"(a), "l"(b))

// ---- fused-kernel shared memory layout (byte offsets) ------------------------------
// Persistent: xw (result), w (swizzled weights), dinv, rowptr, wtmp.
// UNION region: GEMM phase uses it as x-staging (64 KB); afterwards it holds
// offs/csr/nrm for the CSR build + gather.
#define SM_XW    0                          // float[NV*FO]   131072
#define SM_W     (SM_XW   + NV*FO*4)        // float[FO*FI]    16384
#define SM_DINV  (SM_W    + FO*FI*4)        // float[NV]        2048
#define SM_ROWP  (SM_DINV + NV*4)           // int[NV+1]        2052
#define SM_WTMP  ((SM_ROWP + (NV+1)*4 + 15) & ~15)   // int[16]
#define SM_UNION ((SM_WTMP + 64 + 15) & ~15)
#define SM_XSTG  SM_UNION                   // float[256*FI]   65536 (GEMM phase)
#define SM_OFFS  SM_UNION                   // int[NV]          2048 (CSR phase)
#define SM_CSR   (SM_OFFS + NV*4)           // int[NE]         16384
#define SM_NRM   (SM_CSR  + NE*4)           // float[NE]       16384
#define SMEM_TOT (SM_UNION + 256*FI*4)      // ~217 KB

// =====================================================================================
// Fused per-graph kernel, 1024 threads (32 warps -> 8/SMSP for latency hiding).
//   A) GEMM xw = x@W^T in smem: 2 phases x 256 rows, thread tile 8n x 2o (32x32 grid),
//      packed f32x2 over f. a-operand warp-uniform broadcast; b-operand swizzled
//      w_s[o*64 + (f ^ 2*((o>>1)&15))] -> 2-cycle (floor) LDS.64.
//   B) CSR build (histogram, rsqrt-deg, scan, scatter w/ precomputed edge norms)
//      in the union region.
//   C) Gather aggregation: warp per node (16 nodes/warp), lane owns 2 feats,
//      unroll x4 for MLP. (+bias, ReLU) -> g_h.
// =====================================================================================
__global__ __launch_bounds__(1024, 1) void k_fused(const float* __restrict__ x,
                                                   const float* __restrict__ W,
                                                   const int* __restrict__ eidx,
                                                   const float* __restrict__ cbias) {
    extern __shared__ char sm[];
    float* xw_s  = (float*)(sm + SM_XW);
    float* w_s   = (float*)(sm + SM_W);
    float* dinv  = (float*)(sm + SM_DINV);
    int*   rowptr= (int*)  (sm + SM_ROWP);
    int*   wtmp  = (int*)  (sm + SM_WTMP);
    float* xstg  = (float*)(sm + SM_XSTG);
    int*   offs  = (int*)  (sm + SM_OFFS);
    int*   csr   = (int*)  (sm + SM_CSR);
    float* nrmv  = (float*)(sm + SM_NRM);

    const int g    = blockIdx.x;
    const int tid  = threadIdx.x;
    const int lane = tid & 31, wrp = tid >> 5;
    const int* srce = eidx + (size_t)g*2*NE;
    const int* tgte = srce + NE;

    // ---- load W with pair-granular XOR swizzle ----
    for (int i = tid; i < FO*FI/2; i += 1024) {
        int o  = i >> 5;
        int fp = (i & 31) * 2;
        int fs = fp ^ (2*((o >> 1) & 15));
        *(unsigned long long*)&w_s[o*64 + fs] =
            *(const unsigned long long*)&W[o*64 + fp];
    }

    // ---- GEMM: 2 phases of 256 nodes ----
    const int tx = tid & 31;          // o-group (2 outs)
    const int ny = tid >> 5;          // n-group (8 rows) == warp id -> a broadcast
    const int nb = ny * 8, ob = tx * 2, sw = 2 * (tx & 15);

#pragma unroll 1
    for (int p = 0; p < 2; p++) {
        __syncthreads();              // union/xstg reuse boundary
        const float4* xg4 = (const float4*)(x + ((size_t)g*NV + p*256) * FI);
        float4* xs4 = (float4*)xstg;
        for (int i = tid; i < 256*FI/4; i += 1024) xs4[i] = xg4[i];
        __syncthreads();

        unsigned long long acc[8][2];
#pragma unroll
        for (int i = 0; i < 8; i++) { acc[i][0] = 0ull; acc[i][1] = 0ull; }

#pragma unroll
        for (int f = 0; f < 64; f += 4) {
            unsigned long long b0[2], b1[2];
#pragma unroll
            for (int j = 0; j < 2; j++) {
                b0[j] = *(const unsigned long long*)&w_s[(ob+j)*64 + ( f      ^ sw)];
                b1[j] = *(const unsigned long long*)&w_s[(ob+j)*64 + ((f + 2) ^ sw)];
            }
#pragma unroll
            for (int i = 0; i < 8; i++) {
                ulonglong2 a2 = *(const ulonglong2*)&xstg[(nb+i)*64 + f];
                FMA2(acc[i][0], a2.x, b0[0]);
                FMA2(acc[i][1], a2.x, b0[1]);
                FMA2(acc[i][0], a2.y, b1[0]);
                FMA2(acc[i][1], a2.y, b1[1]);
            }
        }
#pragma unroll
        for (int i = 0; i < 8; i++) {
            float2 o2;
            unsigned lo0 = (unsigned)(acc[i][0] & 0xffffffffull);
            unsigned hi0 = (unsigned)(acc[i][0] >> 32);
            unsigned lo1 = (unsigned)(acc[i][1] & 0xffffffffull);
            unsigned hi1 = (unsigned)(acc[i][1] >> 32);
            o2.x = __uint_as_float(lo0) + __uint_as_float(hi0);
            o2.y = __uint_as_float(lo1) + __uint_as_float(hi1);
            *(float2*)&xw_s[(p*256 + nb + i)*64 + ob] = o2;
        }
    }
    __syncthreads();                   // xw_s done; union region free for CSR

    // ---- in-degree histogram ----
    if (tid < NV) offs[tid] = 0;
    __syncthreads();
#pragma unroll
    for (int e = tid; e < NE; e += 1024) atomicAdd(&offs[tgte[e]], 1);
    __syncthreads();

    int cnt = 0;
    if (tid < NV) {
        cnt = offs[tid];
        dinv[tid] = rsqrtf((float)(cnt + 1));   // +1 self-loop
    }

    // ---- block exclusive scan over 512 counts (warps 0..15) ----
    int v = cnt;
#pragma unroll
    for (int d = 1; d < 32; d <<= 1) {
        int t = __shfl_up_sync(0xffffffffu, v, d);
        if (lane >= d) v += t;
    }
    if (lane == 31 && wrp < 16) wtmp[wrp] = v;
    __syncthreads();
    if (wrp == 0) {
        int wv = (lane < 16) ? wtmp[lane] : 0;
#pragma unroll
        for (int d = 1; d < 16; d <<= 1) {
            int t = __shfl_up_sync(0xffffffffu, wv, d);
            if (lane >= d) wv += t;
        }
        if (lane < 16) wtmp[lane] = wv;
    }
    __syncthreads();
    if (tid < NV) {
        const int base = (wrp > 0) ? wtmp[wrp-1] : 0;
        const int excl = base + (v - cnt);
        rowptr[tid] = excl;
        offs[tid]   = excl;
        if (tid == 0) rowptr[NV] = NE;
    }
    __syncthreads();

    // ---- scatter edges sorted by target; precompute edge norms ----
#pragma unroll
    for (int e = tid; e < NE; e += 1024) {
        int s = srce[e], c = tgte[e];
        int p = atomicAdd(&offs[c], 1);
        csr[p]  = s;
        nrmv[p] = dinv[s] * dinv[c];
    }
    __syncthreads();

    // ---- gather aggregation: warp per node (16 per warp), lane owns 2 feats ----
    const float bias0 = cbias[2*lane];
    const float bias1 = cbias[2*lane + 1];
    for (int n = wrp*16; n < wrp*16 + 16; n++) {
        const float d = dinv[n];
        float2 xv = *(const float2*)&xw_s[n*FO + 2*lane];
        float a0 = xv.x * (d*d);
        float a1 = xv.y * (d*d);
        int j = rowptr[n];
        const int end = rowptr[n+1];
        for (; j + 4 <= end; j += 4) {
            int s0 = csr[j],   s1 = csr[j+1], s2 = csr[j+2], s3 = csr[j+3];
            float w0 = nrmv[j], w1 = nrmv[j+1], w2 = nrmv[j+2], w3 = nrmv[j+3];
            float2 m0 = *(const float2*)&xw_s[s0*FO + 2*lane];
            float2 m1 = *(const float2*)&xw_s[s1*FO + 2*lane];
            float2 m2 = *(const float2*)&xw_s[s2*FO + 2*lane];
            float2 m3 = *(const float2*)&xw_s[s3*FO + 2*lane];
            a0 = fmaf(m0.x, w0, a0);  a1 = fmaf(m0.y, w0, a1);
            a0 = fmaf(m1.x, w1, a0);  a1 = fmaf(m1.y, w1, a1);
            a0 = fmaf(m2.x, w2, a0);  a1 = fmaf(m2.y, w2, a1);
            a0 = fmaf(m3.x, w3, a0);  a1 = fmaf(m3.y, w3, a1);
        }
        for (; j < end; j++) {
            int s = csr[j];
            float w = nrmv[j];
            float2 m = *(const float2*)&xw_s[s*FO + 2*lane];
            a0 = fmaf(m.x, w, a0);
            a1 = fmaf(m.y, w, a1);
        }
        float2 o;
        o.x = fmaxf(a0 + bias0, 0.f);
        o.y = fmaxf(a1 + bias1, 0.f);
        *(float2*)&g_h[((size_t)g*NV + n)*FO + 2*lane] = o;
    }
}

// =====================================================================================
// K3: logits split-K, weight-stationary. grid(8 graph-tiles, 64 k-chunks), 256 thr.
// warp w owns k-segment by*512 + w*64; lane = (c = lane&15, kh = lane>>4); thread
// holds w[c][32 k] packed f32x2 in regs; dual acc chains; loops 32 graphs.
// =====================================================================================
__global__ __launch_bounds__(256) void k_lin(const float* __restrict__ lw) {
    const int bx = blockIdx.x;
    const int by = blockIdx.y;
    const int tid = threadIdx.x;
    const int lane = tid & 31, wrp = tid >> 5;
    const int c  = lane & 15;
    const int kh = lane >> 4;
    const int kbase = by*512 + wrp*64 + kh*32;
    const int seg = by*8 + wrp;

    unsigned long long wreg[16];
    const float* wp = lw + (size_t)c*KFLAT + kbase;
#pragma unroll
    for (int p = 0; p < 16; p++)
        wreg[p] = *(const unsigned long long*)&wp[2*p];

    for (int gi = 0; gi < 32; gi++) {
        const int g = bx*32 + gi;
        const float* hp = g_h + (size_t)g*KFLAT + kbase;
        unsigned long long acc0 = 0ull, acc1 = 0ull;
#pragma unroll
        for (int p = 0; p < 4; p++) {
            ulonglong2 ha = *(const ulonglong2*)&hp[8*p];
            ulonglong2 hb = *(const ulonglong2*)&hp[8*p + 4];
            FMA2(acc0, ha.x, wreg[4*p    ]);
            FMA2(acc1, ha.y, wreg[4*p + 1]);
            FMA2(acc0, hb.x, wreg[4*p + 2]);
            FMA2(acc1, hb.y, wreg[4*p + 3]);
        }
        float s = __uint_as_float((unsigned)(acc0 & 0xffffffffull))
                + __uint_as_float((unsigned)(acc0 >> 32))
                + __uint_as_float((unsigned)(acc1 & 0xffffffffull))
                + __uint_as_float((unsigned)(acc1 >> 32));
        s += __shfl_xor_sync(0xffffffffu, s, 16);
        if (kh == 0)
            g_part[((size_t)g*512 + seg)*NC + c] = s;
    }
}

// =====================================================================================
// K4: one block per graph. float4 partial sums, smem tree, + bias, log_softmax.
// =====================================================================================
__global__ __launch_bounds__(256) void k_sm(const float* __restrict__ lbias,
                                            float* __restrict__ out) {
    __shared__ float red[64][16];
    const int g = blockIdx.x;
    const int t = threadIdx.x;
    const int quad = t & 3, sg = t >> 2;

    const float4* pp4 = (const float4*)(g_part + (size_t)g*512*NC);
    float4 acc = make_float4(0.f, 0.f, 0.f, 0.f);
#pragma unroll
    for (int s8 = 0; s8 < 8; s8++) {
        float4 v = pp4[(sg*8 + s8)*4 + quad];
        acc.x += v.x; acc.y += v.y; acc.z += v.z; acc.w += v.w;
    }
    *(float4*)&red[sg][quad*4] = acc;
    __syncthreads();

    if (t < 16) {
        float tot = lbias[t];
#pragma unroll 8
        for (int s = 0; s < 64; s++) tot += red[s][t];

        float m = tot;
#pragma unroll
        for (int d = 8; d >= 1; d >>= 1)
            m = fmaxf(m, __shfl_xor_sync(0x0000ffffu, m, d));
        float e = expf(tot - m);
#pragma unroll
        for (int d = 8; d >= 1; d >>= 1)
            e += __shfl_xor_sync(0x0000ffffu, e, d);

        out[(size_t)g*NC + t] = (tot - m) - logf(e);
    }
}

// =====================================================================================
extern "C" void kernel_launch(void* const* d_in, const int* in_sizes, int n_in,
                              void* d_out, int out_size) {
    const float* x  = (const float*)d_in[0];   // [G,NV,FI]
    const int*   ei = (const int*)  d_in[1];   // [G,2,NE]
    const float* cw = (const float*)d_in[2];   // [FO,FI]
    const float* cb = (const float*)d_in[3];   // [FO]
    const float* lw = (const float*)d_in[4];   // [NC,KFLAT]
    const float* lb = (const float*)d_in[5];   // [NC]
    float* out = (float*)d_out;                // [G,NC]

    (void)in_sizes; (void)n_in; (void)out_size;

    cudaFuncSetAttribute(k_fused, cudaFuncAttributeMaxDynamicSharedMemorySize, SMEM_TOT);

    k_fused<<<G, 1024, SMEM_TOT>>>(x, cw, ei, cb);
    k_lin  <<<dim3(8, 64), 256>>>(lw);
    k_sm   <<<G, 256>>>(lb, out);
}